// round 1
// baseline (speedup 1.0000x reference)
#include <cuda_runtime.h>

// QuantumConvLayer: out[:,2i] = cos(q[2i]) * cos(pi*x[:,2i])
//                   out[:,2i+1] = out[:,2i] * cos(q[2i+1] + pi*x[:,2i+1])
// Pure streaming elementwise map, 256MB in + 256MB out -> HBM-bound.
// One thread per float4 (2 even/odd pairs). __cosf (MUFU) keeps the
// instruction count ~30/thread so the kernel stays memory-bound.

#ifndef QC_PI
#define QC_PI 3.14159265358979323846f
#endif

__global__ void __launch_bounds__(256, 8)
qconv_kernel(const float4* __restrict__ x4,
             const float*  __restrict__ q,
             float4* __restrict__ out4,
             int n4)
{
    int i = blockIdx.x * blockDim.x + threadIdx.x;
    if (i >= n4) return;

    float4 v = x4[i];

    // first element column of this float4 within the 16-wide row
    int c = (i << 2) & 15;

    float qe0 = __ldg(q + c + 0);
    float qo0 = __ldg(q + c + 1);
    float qe1 = __ldg(q + c + 2);
    float qo1 = __ldg(q + c + 3);

    float ze0 = __cosf(qe0) * __cosf(QC_PI * v.x);
    float zo0 = ze0 * __cosf(fmaf(QC_PI, v.y, qo0));
    float ze1 = __cosf(qe1) * __cosf(QC_PI * v.z);
    float zo1 = ze1 * __cosf(fmaf(QC_PI, v.w, qo1));

    out4[i] = make_float4(ze0, zo0, ze1, zo1);
}

extern "C" void kernel_launch(void* const* d_in, const int* in_sizes, int n_in,
                              void* d_out, int out_size)
{
    const float4* x4 = (const float4*)d_in[0];
    const float*  q  = (const float*)d_in[1];
    float4* out4     = (float4*)d_out;

    int n_elems = in_sizes[0];      // B * 16, divisible by 4
    int n4 = n_elems >> 2;

    int threads = 256;
    int blocks  = (n4 + threads - 1) / threads;
    qconv_kernel<<<blocks, threads>>>(x4, q, out4, n4);
}

// round 2
// speedup vs baseline: 1.0051x; 1.0051x over previous
#include <cuda_runtime.h>

// QuantumConvLayer: out[:,2i]   = cos(q[2i]) * cos(pi*x[:,2i])
//                   out[:,2i+1] = out[:,2i]  * cos(q[2i+1] + pi*x[:,2i+1])
// Streaming HBM-bound (256MB in + 256MB out).
// R2: 2x float4 per thread (MLP=2, fewer instr/byte), streaming cache
// hints (__ldcs/__stcs) to stop L2 thrash, vectorized q loads.

#ifndef QC_PI
#define QC_PI 3.14159265358979323846f
#endif

__global__ void __launch_bounds__(256, 8)
qconv_kernel(const float4* __restrict__ x4,
             const float*  __restrict__ q,
             float4* __restrict__ out4,
             int n4)
{
    int t = blockIdx.x * blockDim.x + threadIdx.x;
    int j = t << 1;                 // first float4 index handled by this thread
    if (j >= n4) return;

    // two back-to-back 128-bit streaming loads (MLP=2 before any compute)
    float4 v0 = __ldcs(x4 + j);
    float4 v1 = __ldcs(x4 + j + 1);

    // column of v0.x within the 16-wide row; j is even so c in {0, 8}
    int c = (j << 2) & 15;
    const float4* q4 = (const float4*)(q + c);   // 16B-aligned (c*4 bytes = 0 or 32)
    float4 qa = __ldg(q4);        // q[c .. c+3]   -> pairs for v0
    float4 qb = __ldg(q4 + 1);    // q[c+4 .. c+7] -> pairs for v1

    float ze0 = __cosf(qa.x) * __cosf(QC_PI * v0.x);
    float zo0 = ze0 * __cosf(fmaf(QC_PI, v0.y, qa.y));
    float ze1 = __cosf(qa.z) * __cosf(QC_PI * v0.z);
    float zo1 = ze1 * __cosf(fmaf(QC_PI, v0.w, qa.w));

    float ze2 = __cosf(qb.x) * __cosf(QC_PI * v1.x);
    float zo2 = ze2 * __cosf(fmaf(QC_PI, v1.y, qb.y));
    float ze3 = __cosf(qb.z) * __cosf(QC_PI * v1.z);
    float zo3 = ze3 * __cosf(fmaf(QC_PI, v1.w, qb.w));

    __stcs(out4 + j,     make_float4(ze0, zo0, ze1, zo1));
    __stcs(out4 + j + 1, make_float4(ze2, zo2, ze3, zo3));
}

extern "C" void kernel_launch(void* const* d_in, const int* in_sizes, int n_in,
                              void* d_out, int out_size)
{
    const float4* x4 = (const float4*)d_in[0];
    const float*  q  = (const float*)d_in[1];
    float4* out4     = (float4*)d_out;

    int n_elems = in_sizes[0];   // B * 16
    int n4 = n_elems >> 2;       // float4 count (even)
    int nthreads = n4 >> 1;      // 2 float4s per thread

    int threads = 256;
    int blocks  = (nthreads + threads - 1) / threads;
    qconv_kernel<<<blocks, threads>>>(x4, q, out4, n4);
}